// round 2
// baseline (speedup 1.0000x reference)
#include <cuda_runtime.h>
#include <cuda_bf16.h>
#include <math.h>

// Problem constants
#define BATCH 64
#define TT    48
#define C_IN  64
#define HH    15
#define WW    15
#define PIX   225      // 15*15
#define HID   128
#define SH    17       // padded smem tile edge (15 + 2 halo)

#define SLAB (BATCH * HID * PIX)   // one state buffer: 64*128*225 = 1,843,200 floats

// State scratch (static device globals — no allocation APIs)
__device__ float g_h1[2 * SLAB];
__device__ float g_c1[SLAB];
__device__ float g_h2[2 * SLAB];
__device__ float g_c2[SLAB];

// ---------------------------------------------------------------------------
// Fused conv + LSTM-gate step kernel.
// Block: (tile = blockIdx.x in [0,8), batch b = blockIdx.y).
// Computes, for 16 hidden channels (hc0 = tile*16), all 4 gate pre-activations
// over the full 15x15 image, then does the LSTM update in-register.
// Input channels: [0, CIN_X) from xin, [CIN_X, CIN_X+128) from hin.
// Local output-channel layout: o = j*4 + gate (j in 0..15), global
// oc = gate*128 + hc0 + j   (gates stacked i,f,o,g as in jnp.split).
// ---------------------------------------------------------------------------
template<int CIN_X>
__global__ __launch_bounds__(256, 2)
void convlstm_step_kernel(const float* __restrict__ xin, long xin_bstride,
                          const float* __restrict__ hin,
                          const float* __restrict__ Wt,
                          const float* __restrict__ bias,
                          float* __restrict__ cst,
                          float* __restrict__ hout)
{
    constexpr int CTOT = CIN_X + HID;
    constexpr int CH   = 8;            // channels per smem chunk

    __shared__ float s_in[CH][SH][SH];         // 8*17*17*4  = 9248 B
    __shared__ float s_w[CH * 9 * 64];         // 8*9*64*4   = 18432 B

    const int tile = blockIdx.x;               // 0..7
    const int b    = blockIdx.y;               // 0..63
    const int hc0  = tile * 16;
    const int tid  = threadIdx.x;
    const int tp   = tid & 31;                 // pixel lane
    const int tc   = tid >> 5;                 // oc group (0..7): ocs tc*8 .. tc*8+7

    // Thread pixel set: p = tp + 32*r, r = 0..7
    int  offs[8];
    bool pok[8];
    #pragma unroll
    for (int r = 0; r < 8; r++) {
        int p  = tp + 32 * r;
        pok[r] = (p < PIX);
        int pc = pok[r] ? p : 0;
        int py = pc / 15, px = pc % 15;
        offs[r] = py * SH + px;                // top-left of 3x3 window in padded tile
    }

    float acc[8][8];
    #pragma unroll
    for (int r = 0; r < 8; r++)
        #pragma unroll
        for (int o = 0; o < 8; o++) acc[r][o] = 0.f;

    for (int c0 = 0; c0 < CTOT; c0 += CH) {
        // ---- stage input chunk (zero-padded halo) ----
        const bool from_x = (c0 < CIN_X);
        const float* base = from_x
            ? (xin + (long)b * xin_bstride + (long)c0 * PIX)
            : (hin + ((long)b * HID + (c0 - CIN_X)) * PIX);

        for (int i = tid; i < CH * SH * SH; i += 256) {
            int c  = i / (SH * SH);
            int r2 = i % (SH * SH);
            int yy = r2 / SH, xx = r2 % SH;
            float v = 0.f;
            if (yy >= 1 && yy <= 15 && xx >= 1 && xx <= 15)
                v = base[c * PIX + (yy - 1) * 15 + (xx - 1)];
            s_in[c][yy][xx] = v;
        }
        // ---- stage weight chunk: s_w[(c*9+k)*64 + o], o = j*4+gate ----
        for (int i = tid; i < CH * 9 * 64; i += 256) {
            int o  = i & 63;
            int ck = i >> 6;
            int c  = ck / 9, k = ck % 9;
            int j = o >> 2, gate = o & 3;
            int ocg = gate * HID + hc0 + j;
            s_w[i] = Wt[((long)ocg * CTOT + (c0 + c)) * 9 + k];
        }
        __syncthreads();

        #pragma unroll 1
        for (int c = 0; c < CH; c++) {
            const float* sp = &s_in[c][0][0];
            #pragma unroll
            for (int k = 0; k < 9; k++) {
                const int dy = k / 3, dx = k % 3;
                const float4 w0 = *(const float4*)&s_w[(c * 9 + k) * 64 + tc * 8];
                const float4 w1 = *(const float4*)&s_w[(c * 9 + k) * 64 + tc * 8 + 4];
                #pragma unroll
                for (int r = 0; r < 8; r++) {
                    float a = sp[offs[r] + dy * SH + dx];
                    acc[r][0] += a * w0.x;
                    acc[r][1] += a * w0.y;
                    acc[r][2] += a * w0.z;
                    acc[r][3] += a * w0.w;
                    acc[r][4] += a * w1.x;
                    acc[r][5] += a * w1.y;
                    acc[r][6] += a * w1.z;
                    acc[r][7] += a * w1.w;
                }
            }
        }
        __syncthreads();
    }

    // ---- fused LSTM gate epilogue ----
    // Thread's oc o = tc*8+oi  ->  j = tc*2 + (oi>>2), gate = oi&3
    #pragma unroll
    for (int j2 = 0; j2 < 2; j2++) {
        const int   hc = hc0 + tc * 2 + j2;
        const float bi = bias[0 * HID + hc];
        const float bf = bias[1 * HID + hc];
        const float bo = bias[2 * HID + hc];
        const float bg = bias[3 * HID + hc];
        #pragma unroll
        for (int r = 0; r < 8; r++) {
            if (!pok[r]) continue;
            const int p = tp + 32 * r;
            float zi = acc[r][j2 * 4 + 0] + bi;
            float zf = acc[r][j2 * 4 + 1] + bf;
            float zo = acc[r][j2 * 4 + 2] + bo;
            float zg = acc[r][j2 * 4 + 3] + bg;
            float ig = 1.f / (1.f + expf(-zi));
            float fg = 1.f / (1.f + expf(-zf));
            float og = 1.f / (1.f + expf(-zo));
            float gg = tanhf(zg);
            long idx = ((long)b * HID + hc) * PIX + p;
            float cn = fg * cst[idx] + ig * gg;
            cst[idx]  = cn;
            hout[idx] = og * tanhf(cn);
        }
    }
}

// ---------------------------------------------------------------------------
// Final dense: out[b, o] = sum_k h2[b, k] * Wd[k, o] + bd[o]
// k = hc*225 + p  (matches reshape of [HID, H, W] row-major).
// ---------------------------------------------------------------------------
__global__ __launch_bounds__(128)
void dense_kernel(const float* __restrict__ feat,
                  const float* __restrict__ Wd,
                  const float* __restrict__ bd,
                  float* __restrict__ out)
{
    __shared__ float sf[1024];
    const int b = blockIdx.x;
    const int o = threadIdx.x;
    const float* f = feat + (long)b * (HID * PIX);

    float s0 = 0.f, s1 = 0.f, s2 = 0.f, s3 = 0.f;
    const int KTOT = HID * PIX;                 // 28800
    for (int k0 = 0; k0 < KTOT; k0 += 1024) {
        __syncthreads();
        for (int i = o; i < 1024; i += 128) {
            int k = k0 + i;
            sf[i] = (k < KTOT) ? f[k] : 0.f;
        }
        __syncthreads();
        int kmax = min(1024, KTOT - k0);
        for (int kk = 0; kk < kmax; kk += 4) {
            s0 += sf[kk + 0] * Wd[(long)(k0 + kk + 0) * 128 + o];
            s1 += sf[kk + 1] * Wd[(long)(k0 + kk + 1) * 128 + o];
            s2 += sf[kk + 2] * Wd[(long)(k0 + kk + 2) * 128 + o];
            s3 += sf[kk + 3] * Wd[(long)(k0 + kk + 3) * 128 + o];
        }
    }
    out[b * 128 + o] = (s0 + s1) + (s2 + s3) + bd[o];
}

// ---------------------------------------------------------------------------
extern "C" void kernel_launch(void* const* d_in, const int* in_sizes, int n_in,
                              void* d_out, int out_size)
{
    const float* enc = (const float*)d_in[0];  // [B, T, 64, 15, 15]
    const float* W0  = (const float*)d_in[1];  // [512, 192, 3, 3]
    const float* b0  = (const float*)d_in[2];  // [512]
    const float* W1  = (const float*)d_in[3];  // [512, 256, 3, 3]
    const float* b1  = (const float*)d_in[4];  // [512]
    const float* Wd  = (const float*)d_in[5];  // [28800, 128]
    const float* bd  = (const float*)d_in[6];  // [128]
    float* out = (float*)d_out;                // [64, 128]

    float *h1, *c1, *h2, *c2;
    cudaGetSymbolAddress((void**)&h1, g_h1);
    cudaGetSymbolAddress((void**)&c1, g_c1);
    cudaGetSymbolAddress((void**)&h2, g_h2);
    cudaGetSymbolAddress((void**)&c2, g_c2);

    // Zero initial state (ping-0 of h buffers + cell states)
    cudaMemsetAsync(h1, 0, sizeof(float) * SLAB, 0);
    cudaMemsetAsync(c1, 0, sizeof(float) * SLAB, 0);
    cudaMemsetAsync(h2, 0, sizeof(float) * SLAB, 0);
    cudaMemsetAsync(c2, 0, sizeof(float) * SLAB, 0);

    dim3 grid(8, BATCH);
    const long enc_bstride = (long)TT * C_IN * PIX;   // per-batch stride in encoder_output
    const long h_bstride   = (long)HID * PIX;

    for (int t = 0; t < TT; t++) {
        const int rd = t & 1, wr = rd ^ 1;
        // Layer 0: x = encoder_output[:, t], h = h1[rd] -> h1[wr]
        convlstm_step_kernel<C_IN><<<grid, 256>>>(
            enc + (long)t * C_IN * PIX, enc_bstride,
            h1 + (long)rd * SLAB, W0, b0, c1, h1 + (long)wr * SLAB);
        // Layer 1: x = h1[wr] (fresh), h = h2[rd] -> h2[wr]
        convlstm_step_kernel<HID><<<grid, 256>>>(
            h1 + (long)wr * SLAB, h_bstride,
            h2 + (long)rd * SLAB, W1, b1, c2, h2 + (long)wr * SLAB);
    }
    // After t = 47, fresh h2 lives in ping 0 (wr = (47&1)^1 = 0).
    dense_kernel<<<BATCH, 128>>>(h2, Wd, bd, out);
}

// round 3
// speedup vs baseline: 2.3712x; 2.3712x over previous
#include <cuda_runtime.h>
#include <cuda_bf16.h>
#include <mma.h>
#include <math.h>

using namespace nvcuda;

// ---------------- problem constants ----------------
#define BATCH 64
#define TT    48
#define CIN0  64
#define HID   128
#define PIX   225
#define PP    289                 // padded 17x17 pixels per image
#define MTOT  (BATCH * PP)        // 18496 rows in the implicit-GEMM M dim
#define MT    145                 // ceil(18496/128)
#define NTILES 4                  // 512 gate-cols / 128

// ---------------- smem geometry ----------------
#define AROWS 164                 // 128 + 36 halo rows (tap shifts 0..36)
#define ALDM  40                  // 32 chans + pad (80B rows: LDSM conflict-free)
#define WLDM  136                 // 128 cols + pad (272B rows)
#define ACCLDM 132

#define SMEM_MAIN (2 * AROWS * ALDM * 2 + 9 * 32 * WLDM * 2)   // 104576 B
#define SMEM_EPI  (128 * ACCLDM * 4)                           // 67584 B
#define SMEM_BYTES SMEM_MAIN

// ---------------- device state (no allocation APIs) ----------------
__device__ float g_H1[2][MTOT * HID];
__device__ float g_H2[2][MTOT * HID];
__device__ float g_c1[MTOT * HID];
__device__ float g_c2[MTOT * HID];
__device__ __nv_bfloat16 g_Wp0[18 * 192 * 512];   // [tap][hi/lo][c][n'=hc*4+g]
__device__ __nv_bfloat16 g_Wp1[18 * 256 * 512];

// ---------------------------------------------------------------------------
// Weight prep: split fp32 -> (hi, lo) bf16, reorder to [tap][wk][c][n'],
// with n' = hc*4 + gate so every 128-wide N tile holds all 4 gates of 32 hcs.
// ---------------------------------------------------------------------------
__global__ void prep_w_kernel(const float* __restrict__ W,
                              __nv_bfloat16* __restrict__ Wp, int CTOT)
{
    long idx = (long)blockIdx.x * blockDim.x + threadIdx.x;
    long tot = (long)9 * CTOT * 512;
    if (idx >= tot) return;
    int np  = (int)(idx % 512);
    int c   = (int)((idx / 512) % CTOT);
    int tap = (int)(idx / (512L * CTOT));
    int hc  = np >> 2, gg = np & 3;
    int oc  = gg * HID + hc;
    float w = W[((long)oc * CTOT + c) * 9 + tap];
    __nv_bfloat16 wh = __float2bfloat16(w);
    float wl = w - __bfloat162float(wh);
    Wp[(((long)tap * 2 + 0) * CTOT + c) * 512 + np] = wh;
    Wp[(((long)tap * 2 + 1) * CTOT + c) * 512 + np] = __float2bfloat16(wl);
}

// ---------------------------------------------------------------------------
// Fused step: implicit-GEMM conv (9 shifted taps, 3 split passes) on wmma
// tensor cores + LSTM gate epilogue. Block: 128 M-rows x 128 gate-cols.
// ---------------------------------------------------------------------------
template<int CIN_X, bool FROM_ENC>
__global__ __launch_bounds__(256, 2)
void gemm_step_kernel(const float* __restrict__ xsrc,   // enc(+t) or H slab
                      const float* __restrict__ hsrc,   // recurrent H slab
                      const __nv_bfloat16* __restrict__ Wp,
                      const float* __restrict__ bias,
                      float* __restrict__ cst,
                      float* __restrict__ hout)
{
    constexpr int CTOT = CIN_X + HID;
    constexpr int NKC  = CTOT / 32;

    extern __shared__ char smem[];
    __nv_bfloat16* sAh = (__nv_bfloat16*)smem;           // [AROWS][ALDM]
    __nv_bfloat16* sAl = sAh + AROWS * ALDM;
    __nv_bfloat16* sW  = sAl + AROWS * ALDM;             // [9][32][WLDM]
    float* sAcc = (float*)smem;                          // [128][ACCLDM] (reuse)

    const int m0  = blockIdx.x * 128;
    const int nt  = blockIdx.y;
    const int n0  = nt * 128;
    const int tid = threadIdx.x;
    const int wid = tid >> 5;
    const int wm  = wid >> 1;   // 0..3 : warp M offset wm*32
    const int wn  = wid & 1;    // 0..1 : warp N offset wn*64

    wmma::fragment<wmma::accumulator, 16, 16, 16, float> acc[2][4];
    #pragma unroll
    for (int f = 0; f < 2; f++)
        #pragma unroll
        for (int j = 0; j < 4; j++) wmma::fill_fragment(acc[f][j], 0.f);

    for (int kc = 0; kc < NKC; kc++) {
        const int cg = kc * 32;
        __syncthreads();   // previous iteration's reads done before overwrite

        // ---- stage A chunk (hi & lo) : rows m0-18 .. m0+145 ----
        for (int u = tid; u < AROWS * 8; u += 256) {
            int r = u >> 3, q = u & 7;
            int g = m0 - 18 + r;
            float v0 = 0.f, v1 = 0.f, v2 = 0.f, v3 = 0.f;
            if ((unsigned)g < (unsigned)MTOT) {
                if (FROM_ENC && cg < CIN_X) {
                    int b = g / PP, pid = g % PP;
                    int y = pid / 17, x = pid % 17;
                    if (y >= 1 && y <= 15 && x >= 1 && x <= 15) {
                        const float* p = xsrc + ((long)b * TT * CIN0 + (cg + q * 4)) * PIX
                                              + (y - 1) * 15 + (x - 1);
                        v0 = p[0]; v1 = p[PIX]; v2 = p[2 * PIX]; v3 = p[3 * PIX];
                    }
                } else {
                    const float* p = (cg < CIN_X)
                        ? (xsrc + (long)g * HID + (cg - (FROM_ENC ? 0 : 0)) + q * 4)
                        : (hsrc + (long)g * HID + (cg - CIN_X) + q * 4);
                    float4 f4 = *(const float4*)p;
                    v0 = f4.x; v1 = f4.y; v2 = f4.z; v3 = f4.w;
                }
            }
            __nv_bfloat16* dh = &sAh[r * ALDM + q * 4];
            __nv_bfloat16* dl = &sAl[r * ALDM + q * 4];
            float vv[4] = {v0, v1, v2, v3};
            #pragma unroll
            for (int i = 0; i < 4; i++) {
                __nv_bfloat16 hi = __float2bfloat16(vv[i]);
                dh[i] = hi;
                dl[i] = __float2bfloat16(vv[i] - __bfloat162float(hi));
            }
        }

        // ---- stage W (hi) for all 9 taps ----
        for (int u = tid; u < 9 * 32 * 16; u += 256) {
            int nlv = (u & 15) * 8;
            int kr  = (u >> 4) & 31;
            int tap = u >> 9;
            const __nv_bfloat16* src =
                Wp + (((long)tap * 2 + 0) * CTOT + cg + kr) * 512 + n0 + nlv;
            *(uint4*)&sW[(tap * 32 + kr) * WLDM + nlv] = *(const uint4*)src;
        }
        __syncthreads();

        // ---- passes: (Ah,Wh) then (Al,Wh) ----
        #pragma unroll
        for (int half = 0; half < 2; half++) {
            const __nv_bfloat16* sA = half ? sAl : sAh;
            #pragma unroll 1
            for (int tap = 0; tap < 9; tap++) {
                const int shift = (tap / 3) * 17 + (tap % 3);   // s + 18
                #pragma unroll
                for (int ks = 0; ks < 2; ks++) {
                    wmma::fragment<wmma::matrix_b, 16, 16, 16, __nv_bfloat16,
                                   wmma::row_major> bfr[4];
                    #pragma unroll
                    for (int j = 0; j < 4; j++)
                        wmma::load_matrix_sync(bfr[j],
                            sW + (tap * 32 + ks * 16) * WLDM + wn * 64 + j * 16, WLDM);
                    #pragma unroll
                    for (int f = 0; f < 2; f++) {
                        wmma::fragment<wmma::matrix_a, 16, 16, 16, __nv_bfloat16,
                                       wmma::row_major> afr;
                        wmma::load_matrix_sync(afr,
                            sA + (wm * 32 + f * 16 + shift) * ALDM + ks * 16, ALDM);
                        #pragma unroll
                        for (int j = 0; j < 4; j++)
                            wmma::mma_sync(acc[f][j], afr, bfr[j], acc[f][j]);
                    }
                }
            }
        }
        __syncthreads();

        // ---- stage W (lo), then pass (Ah,Wl) ----
        for (int u = tid; u < 9 * 32 * 16; u += 256) {
            int nlv = (u & 15) * 8;
            int kr  = (u >> 4) & 31;
            int tap = u >> 9;
            const __nv_bfloat16* src =
                Wp + (((long)tap * 2 + 1) * CTOT + cg + kr) * 512 + n0 + nlv;
            *(uint4*)&sW[(tap * 32 + kr) * WLDM + nlv] = *(const uint4*)src;
        }
        __syncthreads();

        #pragma unroll 1
        for (int tap = 0; tap < 9; tap++) {
            const int shift = (tap / 3) * 17 + (tap % 3);
            #pragma unroll
            for (int ks = 0; ks < 2; ks++) {
                wmma::fragment<wmma::matrix_b, 16, 16, 16, __nv_bfloat16,
                               wmma::row_major> bfr[4];
                #pragma unroll
                for (int j = 0; j < 4; j++)
                    wmma::load_matrix_sync(bfr[j],
                        sW + (tap * 32 + ks * 16) * WLDM + wn * 64 + j * 16, WLDM);
                #pragma unroll
                for (int f = 0; f < 2; f++) {
                    wmma::fragment<wmma::matrix_a, 16, 16, 16, __nv_bfloat16,
                                   wmma::row_major> afr;
                    wmma::load_matrix_sync(afr,
                        sAh + (wm * 32 + f * 16 + shift) * ALDM + ks * 16, ALDM);
                    #pragma unroll
                    for (int j = 0; j < 4; j++)
                        wmma::mma_sync(acc[f][j], afr, bfr[j], acc[f][j]);
                }
            }
        }
    }

    // ---- epilogue: acc -> smem (known layout) -> LSTM update ----
    __syncthreads();
    #pragma unroll
    for (int f = 0; f < 2; f++)
        #pragma unroll
        for (int j = 0; j < 4; j++)
            wmma::store_matrix_sync(sAcc + (wm * 32 + f * 16) * ACCLDM + wn * 64 + j * 16,
                                    acc[f][j], ACCLDM, wmma::mem_row_major);
    __syncthreads();

    for (int e = tid; e < 128 * 32; e += 256) {
        int mr = e >> 5, hcl = e & 31;
        int m = m0 + mr;
        if (m >= MTOT) continue;
        int pid = m % PP;
        int y = pid / 17, x = pid % 17;
        if (y < 1 || y > 15 || x < 1 || x > 15) continue;   // ring rows stay zero
        int hc = nt * 32 + hcl;
        const float* zr = &sAcc[mr * ACCLDM + hcl * 4];
        float zi = zr[0] + bias[hc];
        float zf = zr[1] + bias[HID + hc];
        float zo = zr[2] + bias[2 * HID + hc];
        float zg = zr[3] + bias[3 * HID + hc];
        float ig = __fdividef(1.f, 1.f + __expf(-zi));
        float fg = __fdividef(1.f, 1.f + __expf(-zf));
        float og = __fdividef(1.f, 1.f + __expf(-zo));
        float eg = __expf(2.f * zg);
        float gg = 1.f - __fdividef(2.f, eg + 1.f);         // tanh, inf-safe
        long idx = (long)m * HID + hc;
        float cn = fg * cst[idx] + ig * gg;
        cst[idx] = cn;
        float ec = __expf(2.f * cn);
        float th = 1.f - __fdividef(2.f, ec + 1.f);
        hout[idx] = og * th;
    }
}

// ---------------------------------------------------------------------------
// Final dense (exact fp32): out[b,o] = feat . Wd + bd, feat gathered from the
// padded-row H2 layout.
// ---------------------------------------------------------------------------
__global__ __launch_bounds__(128)
void dense_kernel(const float* __restrict__ H2f,
                  const float* __restrict__ Wd,
                  const float* __restrict__ bd,
                  float* __restrict__ out)
{
    __shared__ float sf[1024];
    const int b = blockIdx.x;
    const int o = threadIdx.x;
    float s0 = 0.f, s1 = 0.f, s2 = 0.f, s3 = 0.f;
    const int KTOT = HID * PIX;
    for (int k0 = 0; k0 < KTOT; k0 += 1024) {
        __syncthreads();
        for (int i = o; i < 1024; i += 128) {
            int k = k0 + i;
            float v = 0.f;
            if (k < KTOT) {
                int hc = k / PIX, p = k % PIX;
                int m = b * PP + (p / 15 + 1) * 17 + (p % 15 + 1);
                v = H2f[(long)m * HID + hc];
            }
            sf[i] = v;
        }
        __syncthreads();
        int kmax = min(1024, KTOT - k0);
        for (int kk = 0; kk < kmax; kk += 4) {
            s0 += sf[kk + 0] * Wd[(long)(k0 + kk + 0) * 128 + o];
            s1 += sf[kk + 1] * Wd[(long)(k0 + kk + 1) * 128 + o];
            s2 += sf[kk + 2] * Wd[(long)(k0 + kk + 2) * 128 + o];
            s3 += sf[kk + 3] * Wd[(long)(k0 + kk + 3) * 128 + o];
        }
    }
    out[b * 128 + o] = (s0 + s1) + (s2 + s3) + bd[o];
}

// ---------------------------------------------------------------------------
extern "C" void kernel_launch(void* const* d_in, const int* in_sizes, int n_in,
                              void* d_out, int out_size)
{
    const float* enc = (const float*)d_in[0];  // [B, T, 64, 15, 15]
    const float* W0  = (const float*)d_in[1];
    const float* b0  = (const float*)d_in[2];
    const float* W1  = (const float*)d_in[3];
    const float* b1  = (const float*)d_in[4];
    const float* Wd  = (const float*)d_in[5];
    const float* bd  = (const float*)d_in[6];
    float* out = (float*)d_out;

    float *H1, *H2, *c1, *c2;
    __nv_bfloat16 *Wp0, *Wp1;
    cudaGetSymbolAddress((void**)&H1, g_H1);
    cudaGetSymbolAddress((void**)&H2, g_H2);
    cudaGetSymbolAddress((void**)&c1, g_c1);
    cudaGetSymbolAddress((void**)&c2, g_c2);
    cudaGetSymbolAddress((void**)&Wp0, g_Wp0);
    cudaGetSymbolAddress((void**)&Wp1, g_Wp1);

    const long SLABF = (long)MTOT * HID;          // floats per state slab
    cudaMemsetAsync(H1, 0, sizeof(float) * 2 * SLABF, 0);
    cudaMemsetAsync(H2, 0, sizeof(float) * 2 * SLABF, 0);
    cudaMemsetAsync(c1, 0, sizeof(float) * SLABF, 0);
    cudaMemsetAsync(c2, 0, sizeof(float) * SLABF, 0);

    prep_w_kernel<<<(9 * 192 * 512 + 255) / 256, 256>>>(W0, Wp0, 192);
    prep_w_kernel<<<(9 * 256 * 512 + 255) / 256, 256>>>(W1, Wp1, 256);

    cudaFuncSetAttribute(gemm_step_kernel<CIN0, true>,
                         cudaFuncAttributeMaxDynamicSharedMemorySize, SMEM_BYTES);
    cudaFuncSetAttribute(gemm_step_kernel<HID, false>,
                         cudaFuncAttributeMaxDynamicSharedMemorySize, SMEM_BYTES);

    dim3 grid(MT, NTILES);
    for (int t = 0; t < TT; t++) {
        const int rd = t & 1, wr = rd ^ 1;
        gemm_step_kernel<CIN0, true><<<grid, 256, SMEM_BYTES>>>(
            enc + (long)t * CIN0 * PIX, H1 + (long)rd * SLABF,
            Wp0, b0, c1, H1 + (long)wr * SLABF);
        gemm_step_kernel<HID, false><<<grid, 256, SMEM_BYTES>>>(
            H1 + (long)wr * SLABF, H2 + (long)rd * SLABF,
            Wp1, b1, c2, H2 + (long)wr * SLABF);
    }
    // final h2 is in ping 0 (wr of t=47)
    dense_kernel<<<BATCH, 128>>>(H2, Wd, bd, out);
}

// round 5
// speedup vs baseline: 2.7792x; 1.1721x over previous
#include <cuda_runtime.h>
#include <cuda_bf16.h>
#include <mma.h>
#include <math.h>
#include <cstdint>

using namespace nvcuda;

// ---------------- problem constants ----------------
#define BATCH 64
#define TT    48
#define PIX   225
#define PP    289                    // padded 17x17 pixels per image
#define MTOT  (BATCH * PP)           // 18496
#define HID   128
#define MT    145                    // ceil(18496/128)

// ---------------- smem geometry ----------------
#define AROWS 164                    // 128 + 36 halo rows
#define ALDM  40                     // 32 ch + pad
#define WLDM  136                    // 128 cols + pad
#define ACCLDM 132
#define SMEM_BYTES (2 * AROWS * ALDM * 2 + 9 * 32 * WLDM * 2)   // 104576

// ---------------- device state (no allocation APIs) ----------------
__device__ __nv_bfloat16 g_enc_h[(size_t)TT * MTOT * 64];
__device__ __nv_bfloat16 g_enc_l[(size_t)TT * MTOT * 64];
__device__ __nv_bfloat16 g_h1h[2][(size_t)MTOT * HID];
__device__ __nv_bfloat16 g_h1l[2][(size_t)MTOT * HID];
__device__ __nv_bfloat16 g_h2h[2][(size_t)MTOT * HID];
__device__ __nv_bfloat16 g_h2l[2][(size_t)MTOT * HID];
__device__ float g_c1[(size_t)MTOT * HID];
__device__ float g_c2[(size_t)MTOT * HID];
// weights: [kc32][tap][pass(hi/lo)][k(32)][n'(512)]  with n' = hc*4 + gate
__device__ __nv_bfloat16 g_Wp0[(size_t)6 * 9 * 2 * 32 * 512];
__device__ __nv_bfloat16 g_Wp1[(size_t)8 * 9 * 2 * 32 * 512];

// ---------------------------------------------------------------------------
// prep: weights -> split hi/lo bf16, reorder
// ---------------------------------------------------------------------------
__global__ void prep_w(const float* __restrict__ W, __nv_bfloat16* __restrict__ Wp,
                       int NKC)
{
    const int CTOT = NKC * 32;
    long idx = (long)blockIdx.x * blockDim.x + threadIdx.x;
    long tot = (long)NKC * 9 * 32 * 512;
    if (idx >= tot) return;
    int n   = (int)(idx & 511);
    int k   = (int)((idx >> 9) & 31);
    int tap = (int)((idx >> 14) % 9);
    int kc  = (int)(idx / (9L << 14));
    int hc = n >> 2, gate = n & 3;
    int oc = gate * HID + hc;
    int c  = kc * 32 + k;
    float w = W[((long)oc * CTOT + c) * 9 + tap];
    __nv_bfloat16 hi = __float2bfloat16(w);
    __nv_bfloat16 lo = __float2bfloat16(w - __bfloat162float(hi));
    size_t base = ((size_t)(kc * 9 + tap) * 2) * (32 * 512) + (size_t)k * 512 + n;
    Wp[base]            = hi;
    Wp[base + 32 * 512] = lo;
}

// ---------------------------------------------------------------------------
// prep: encoder -> padded-row [t][m][64] split hi/lo (ring rows zero)
// ---------------------------------------------------------------------------
__global__ void prep_enc(const float* __restrict__ enc,
                         __nv_bfloat16* __restrict__ eh, __nv_bfloat16* __restrict__ el)
{
    size_t idx = (size_t)blockIdx.x * blockDim.x + threadIdx.x;
    size_t tot = (size_t)TT * MTOT * 64;
    if (idx >= tot) return;
    int c = (int)(idx & 63);
    int m = (int)((idx >> 6) % MTOT);
    int t = (int)(idx / ((size_t)MTOT * 64));
    int b = m / PP, pid = m % PP;
    int y = pid / 17, x = pid % 17;
    float v = 0.f;
    if (y >= 1 && y <= 15 && x >= 1 && x <= 15)
        v = enc[(((size_t)b * TT + t) * 64 + c) * PIX + (y - 1) * 15 + (x - 1)];
    __nv_bfloat16 hi = __float2bfloat16(v);
    eh[idx] = hi;
    el[idx] = __float2bfloat16(v - __bfloat162float(hi));
}

// ---------------------------------------------------------------------------
// Fused step: implicit-GEMM conv (9 shifted taps, 3 split passes) + LSTM gates.
// Block: 128 threads / 4 warps, tile 128M x 128N, warp tile 64x64.
// Grid (145, 4). 2 CTAs/SM.
// ---------------------------------------------------------------------------
template<int NKC, int NX, int XSTR>
__global__ __launch_bounds__(128, 2)
void step_kernel(const __nv_bfloat16* __restrict__ xh, const __nv_bfloat16* __restrict__ xl,
                 const __nv_bfloat16* __restrict__ hh, const __nv_bfloat16* __restrict__ hl,
                 const __nv_bfloat16* __restrict__ Wp, const float* __restrict__ bias,
                 float* __restrict__ cst,
                 __nv_bfloat16* __restrict__ oh, __nv_bfloat16* __restrict__ ol)
{
    extern __shared__ __align__(16) __nv_bfloat16 smem[];
    __nv_bfloat16* sAh = smem;                       // [164][40]
    __nv_bfloat16* sAl = sAh + AROWS * ALDM;
    __nv_bfloat16* sW  = sAl + AROWS * ALDM;         // [9][32][136]
    float* sAcc = (float*)smem;                      // reuse for epilogue

    const int m0  = blockIdx.x * 128;
    const int nt  = blockIdx.y;
    const int n0  = nt * 128;
    const int tid = threadIdx.x;
    const int wid = tid >> 5;
    const int wm  = wid >> 1;     // 0..1 : warp M offset wm*64
    const int wn  = wid & 1;      // 0..1 : warp N offset wn*64

    wmma::fragment<wmma::accumulator, 16, 16, 16, float> acc[4][4];
    #pragma unroll
    for (int f = 0; f < 4; f++)
        #pragma unroll
        for (int j = 0; j < 4; j++) wmma::fill_fragment(acc[f][j], 0.f);

    for (int kc = 0; kc < NKC; kc++) {
        // ---- stage A (hi/lo): rows m0-18 .. m0+145, 32 channels ----
        const __nv_bfloat16 *bh_, *bl_; int coff, stride;
        if (kc < NX) { bh_ = xh; bl_ = xl; coff = kc * 32; stride = XSTR; }
        else         { bh_ = hh; bl_ = hl; coff = (kc - NX) * 32; stride = HID; }
        for (int u = tid; u < AROWS * 4; u += 128) {
            int r = u >> 2, q = u & 3;
            int m = m0 - 18 + r;
            uint4 vh = make_uint4(0, 0, 0, 0), vl = vh;
            if (m >= 0 && m < MTOT) {
                size_t eo = (size_t)m * stride + coff + q * 8;
                vh = *(const uint4*)(bh_ + eo);
                vl = *(const uint4*)(bl_ + eo);
            }
            *(uint4*)(sAh + r * ALDM + q * 8) = vh;
            *(uint4*)(sAl + r * ALDM + q * 8) = vl;
        }
        // ---- stage W hi for all 9 taps (128-col slice) ----
        for (int u = tid; u < 9 * 32 * 16; u += 128) {
            int nl  = (u & 15) * 8;
            int kr  = (u >> 4) & 31;
            int tap = u >> 9;
            const __nv_bfloat16* s =
                Wp + ((size_t)((kc * 9 + tap) * 2 + 0)) * (32 * 512) + (size_t)kr * 512 + n0 + nl;
            *(uint4*)(sW + (tap * 32 + kr) * WLDM + nl) = *(const uint4*)s;
        }
        __syncthreads();

        // ---- passes 1+2: (Ah*Wh) and (Al*Wh), sharing B fragments ----
        #pragma unroll 1
        for (int tap = 0; tap < 9; tap++) {
            const int s = (tap / 3) * 17 + (tap % 3);
            #pragma unroll
            for (int ks = 0; ks < 2; ks++) {
                wmma::fragment<wmma::matrix_b, 16, 16, 16, __nv_bfloat16, wmma::row_major> bf[4];
                #pragma unroll
                for (int j = 0; j < 4; j++)
                    wmma::load_matrix_sync(bf[j],
                        sW + (tap * 32 + ks * 16) * WLDM + wn * 64 + j * 16, WLDM);
                wmma::fragment<wmma::matrix_a, 16, 16, 16, __nv_bfloat16, wmma::row_major> af[4];
                #pragma unroll
                for (int f = 0; f < 4; f++)
                    wmma::load_matrix_sync(af[f],
                        sAh + (wm * 64 + f * 16 + s) * ALDM + ks * 16, ALDM);
                #pragma unroll
                for (int f = 0; f < 4; f++)
                    #pragma unroll
                    for (int j = 0; j < 4; j++)
                        wmma::mma_sync(acc[f][j], af[f], bf[j], acc[f][j]);
                #pragma unroll
                for (int f = 0; f < 4; f++)
                    wmma::load_matrix_sync(af[f],
                        sAl + (wm * 64 + f * 16 + s) * ALDM + ks * 16, ALDM);
                #pragma unroll
                for (int f = 0; f < 4; f++)
                    #pragma unroll
                    for (int j = 0; j < 4; j++)
                        wmma::mma_sync(acc[f][j], af[f], bf[j], acc[f][j]);
            }
        }
        __syncthreads();

        // ---- stage W lo, pass 3: (Ah*Wl) ----
        for (int u = tid; u < 9 * 32 * 16; u += 128) {
            int nl  = (u & 15) * 8;
            int kr  = (u >> 4) & 31;
            int tap = u >> 9;
            const __nv_bfloat16* s =
                Wp + ((size_t)((kc * 9 + tap) * 2 + 1)) * (32 * 512) + (size_t)kr * 512 + n0 + nl;
            *(uint4*)(sW + (tap * 32 + kr) * WLDM + nl) = *(const uint4*)s;
        }
        __syncthreads();

        #pragma unroll 1
        for (int tap = 0; tap < 9; tap++) {
            const int s = (tap / 3) * 17 + (tap % 3);
            #pragma unroll
            for (int ks = 0; ks < 2; ks++) {
                wmma::fragment<wmma::matrix_b, 16, 16, 16, __nv_bfloat16, wmma::row_major> bf[4];
                #pragma unroll
                for (int j = 0; j < 4; j++)
                    wmma::load_matrix_sync(bf[j],
                        sW + (tap * 32 + ks * 16) * WLDM + wn * 64 + j * 16, WLDM);
                wmma::fragment<wmma::matrix_a, 16, 16, 16, __nv_bfloat16, wmma::row_major> af[4];
                #pragma unroll
                for (int f = 0; f < 4; f++)
                    wmma::load_matrix_sync(af[f],
                        sAh + (wm * 64 + f * 16 + s) * ALDM + ks * 16, ALDM);
                #pragma unroll
                for (int f = 0; f < 4; f++)
                    #pragma unroll
                    for (int j = 0; j < 4; j++)
                        wmma::mma_sync(acc[f][j], af[f], bf[j], acc[f][j]);
            }
        }
        __syncthreads();
    }

    // ---- epilogue: acc -> smem -> LSTM update -> split bf16 state ----
    #pragma unroll
    for (int f = 0; f < 4; f++)
        #pragma unroll
        for (int j = 0; j < 4; j++)
            wmma::store_matrix_sync(sAcc + (wm * 64 + f * 16) * ACCLDM + wn * 64 + j * 16,
                                    acc[f][j], ACCLDM, wmma::mem_row_major);
    __syncthreads();

    for (int e = tid; e < 128 * 32; e += 128) {
        int mr = e >> 5, hcl = e & 31;
        int m = m0 + mr;
        if (m >= MTOT) continue;
        int pid = m % PP;
        int y = pid / 17, x = pid % 17;
        if (y < 1 || y > 15 || x < 1 || x > 15) continue;   // ring rows stay zero
        int hc = nt * 32 + hcl;
        const float* zr = &sAcc[mr * ACCLDM + hcl * 4];
        float zi = zr[0] + bias[hc];
        float zf = zr[1] + bias[HID + hc];
        float zo = zr[2] + bias[2 * HID + hc];
        float zg = zr[3] + bias[3 * HID + hc];
        float ig = __fdividef(1.f, 1.f + __expf(-zi));
        float fg = __fdividef(1.f, 1.f + __expf(-zf));
        float og = __fdividef(1.f, 1.f + __expf(-zo));
        float eg = __expf(2.f * zg);
        float gg = 1.f - __fdividef(2.f, eg + 1.f);         // tanh, inf-safe
        size_t idx = (size_t)m * HID + hc;
        float cn = fg * cst[idx] + ig * gg;
        cst[idx] = cn;
        float ec = __expf(2.f * cn);
        float hv = og * (1.f - __fdividef(2.f, ec + 1.f));
        __nv_bfloat16 hi = __float2bfloat16(hv);
        oh[idx] = hi;
        ol[idx] = __float2bfloat16(hv - __bfloat162float(hi));
    }
}

// ---------------------------------------------------------------------------
// Final dense (exact fp32): out[b,o] = feat . Wd + bd, feat = h2 hi+lo.
// ---------------------------------------------------------------------------
__global__ __launch_bounds__(128)
void dense_kernel(const __nv_bfloat16* __restrict__ h2h,
                  const __nv_bfloat16* __restrict__ h2l,
                  const float* __restrict__ Wd, const float* __restrict__ bd,
                  float* __restrict__ out)
{
    __shared__ float sf[1024];
    const int b = blockIdx.x;
    const int o = threadIdx.x;
    float s0 = 0.f, s1 = 0.f, s2 = 0.f, s3 = 0.f;
    const int KTOT = HID * PIX;                // 28800
    for (int k0 = 0; k0 < KTOT; k0 += 1024) {
        __syncthreads();
        for (int i = o; i < 1024; i += 128) {
            int k = k0 + i;
            float v = 0.f;
            if (k < KTOT) {
                int hc = k / PIX, p = k % PIX;
                size_t m = (size_t)b * PP + (p / 15 + 1) * 17 + (p % 15 + 1);
                size_t idx = m * HID + hc;
                v = __bfloat162float(h2h[idx]) + __bfloat162float(h2l[idx]);
            }
            sf[i] = v;
        }
        __syncthreads();
        int kmax = min(1024, KTOT - k0);
        for (int kk = 0; kk < kmax; kk += 4) {
            s0 += sf[kk + 0] * Wd[(long)(k0 + kk + 0) * 128 + o];
            s1 += sf[kk + 1] * Wd[(long)(k0 + kk + 1) * 128 + o];
            s2 += sf[kk + 2] * Wd[(long)(k0 + kk + 2) * 128 + o];
            s3 += sf[kk + 3] * Wd[(long)(k0 + kk + 3) * 128 + o];
        }
    }
    out[b * 128 + o] = (s0 + s1) + (s2 + s3) + bd[o];
}

// ---------------------------------------------------------------------------
extern "C" void kernel_launch(void* const* d_in, const int* in_sizes, int n_in,
                              void* d_out, int out_size)
{
    const float* enc = (const float*)d_in[0];
    const float* W0  = (const float*)d_in[1];
    const float* b0  = (const float*)d_in[2];
    const float* W1  = (const float*)d_in[3];
    const float* b1  = (const float*)d_in[4];
    const float* Wd  = (const float*)d_in[5];
    const float* bd  = (const float*)d_in[6];
    float* out = (float*)d_out;

    __nv_bfloat16 *eh, *el, *h1h, *h1l, *h2h, *h2l, *Wp0, *Wp1;
    float *c1, *c2;
    cudaGetSymbolAddress((void**)&eh, g_enc_h);
    cudaGetSymbolAddress((void**)&el, g_enc_l);
    cudaGetSymbolAddress((void**)&h1h, g_h1h);
    cudaGetSymbolAddress((void**)&h1l, g_h1l);
    cudaGetSymbolAddress((void**)&h2h, g_h2h);
    cudaGetSymbolAddress((void**)&h2l, g_h2l);
    cudaGetSymbolAddress((void**)&c1, g_c1);
    cudaGetSymbolAddress((void**)&c2, g_c2);
    cudaGetSymbolAddress((void**)&Wp0, g_Wp0);
    cudaGetSymbolAddress((void**)&Wp1, g_Wp1);

    const size_t HS = (size_t)MTOT * HID;

    cudaMemsetAsync(h1h, 0, 2 * HS * sizeof(__nv_bfloat16), 0);
    cudaMemsetAsync(h1l, 0, 2 * HS * sizeof(__nv_bfloat16), 0);
    cudaMemsetAsync(h2h, 0, 2 * HS * sizeof(__nv_bfloat16), 0);
    cudaMemsetAsync(h2l, 0, 2 * HS * sizeof(__nv_bfloat16), 0);
    cudaMemsetAsync(c1, 0, HS * sizeof(float), 0);
    cudaMemsetAsync(c2, 0, HS * sizeof(float), 0);

    prep_w<<<(6 * 9 * 32 * 512 + 255) / 256, 256>>>(W0, Wp0, 6);
    prep_w<<<(8 * 9 * 32 * 512 + 255) / 256, 256>>>(W1, Wp1, 8);
    {
        size_t tot = (size_t)TT * MTOT * 64;
        prep_enc<<<(unsigned)((tot + 255) / 256), 256>>>(enc, eh, el);
    }

    cudaFuncSetAttribute(step_kernel<6, 2, 64>,
                         cudaFuncAttributeMaxDynamicSharedMemorySize, SMEM_BYTES);
    cudaFuncSetAttribute(step_kernel<8, 4, 128>,
                         cudaFuncAttributeMaxDynamicSharedMemorySize, SMEM_BYTES);

    dim3 grid(MT, 4);
    for (int t = 0; t < TT; t++) {
        const int rd = t & 1, wr = rd ^ 1;
        step_kernel<6, 2, 64><<<grid, 128, SMEM_BYTES>>>(
            eh + (size_t)t * MTOT * 64, el + (size_t)t * MTOT * 64,
            h1h + (size_t)rd * HS, h1l + (size_t)rd * HS,
            Wp0, b0, c1,
            h1h + (size_t)wr * HS, h1l + (size_t)wr * HS);
        step_kernel<8, 4, 128><<<grid, 128, SMEM_BYTES>>>(
            h1h + (size_t)wr * HS, h1l + (size_t)wr * HS,
            h2h + (size_t)rd * HS, h2l + (size_t)rd * HS,
            Wp1, b1, c2,
            h2h + (size_t)wr * HS, h2l + (size_t)wr * HS);
    }
    // final h2 in ping 0 (wr of t=47)
    dense_kernel<<<BATCH, 128>>>(h2h, h2l, Wd, bd, out);
}

// round 6
// speedup vs baseline: 4.0943x; 1.4732x over previous
#include <cuda_runtime.h>
#include <cuda_fp16.h>
#include <mma.h>
#include <math.h>
#include <cstdint>

using namespace nvcuda;

// ---------------- problem constants ----------------
#define BATCH 64
#define TT    48
#define PIX   225
#define PP    289                    // padded 17x17 pixels per image
#define MTOT  (BATCH * PP)           // 18496
#define HID   128
#define MT    145                    // ceil(18496/128)

#define WSCALE   64.0f
#define INVSCALE 0.015625f

// ---------------- smem geometry ----------------
#define AROWS 164                    // 128 + 36 halo rows
#define ALDM  40                     // 32 ch + pad
#define WLDM  136                    // 128 cols + pad
#define ACCLDM 132
#define SMEM_BYTES (AROWS * ALDM * 2 + 9 * 32 * WLDM * 2)   // 91456

// ---------------- device state (no allocation APIs) ----------------
__device__ __half g_enc[(size_t)TT * MTOT * 64];
__device__ __half g_h1[2][(size_t)MTOT * HID];
__device__ __half g_h2[2][(size_t)MTOT * HID];
__device__ float g_c1[(size_t)MTOT * HID];
__device__ float g_c2[(size_t)MTOT * HID];
// weights: [kc32][tap][pass(hi/lo)][k(32)][n'(512)]  with n' = hc*4 + gate
__device__ __half g_Wp0[(size_t)6 * 9 * 2 * 32 * 512];
__device__ __half g_Wp1[(size_t)8 * 9 * 2 * 32 * 512];

// ---------------------------------------------------------------------------
// prep: weights -> scaled fp16 hi/lo split, reorder
// ---------------------------------------------------------------------------
__global__ void prep_w(const float* __restrict__ W, __half* __restrict__ Wp,
                       int NKC)
{
    const int CTOT = NKC * 32;
    long idx = (long)blockIdx.x * blockDim.x + threadIdx.x;
    long tot = (long)NKC * 9 * 32 * 512;
    if (idx >= tot) return;
    int n   = (int)(idx & 511);
    int k   = (int)((idx >> 9) & 31);
    int tap = (int)((idx >> 14) % 9);
    int kc  = (int)(idx / (9L << 14));
    int hc = n >> 2, gate = n & 3;
    int oc = gate * HID + hc;
    int c  = kc * 32 + k;
    float w = W[((long)oc * CTOT + c) * 9 + tap] * WSCALE;
    __half hi = __float2half(w);
    __half lo = __float2half(w - __half2float(hi));
    size_t base = ((size_t)(kc * 9 + tap) * 2) * (32 * 512) + (size_t)k * 512 + n;
    Wp[base]            = hi;
    Wp[base + 32 * 512] = lo;
}

// ---------------------------------------------------------------------------
// prep: encoder -> padded-row [t][m][64] fp16 (ring rows zero)
// ---------------------------------------------------------------------------
__global__ void prep_enc(const float* __restrict__ enc, __half* __restrict__ e16)
{
    size_t idx = (size_t)blockIdx.x * blockDim.x + threadIdx.x;
    size_t tot = (size_t)TT * MTOT * 64;
    if (idx >= tot) return;
    int c = (int)(idx & 63);
    int m = (int)((idx >> 6) % MTOT);
    int t = (int)(idx / ((size_t)MTOT * 64));
    int b = m / PP, pid = m % PP;
    int y = pid / 17, x = pid % 17;
    float v = 0.f;
    if (y >= 1 && y <= 15 && x >= 1 && x <= 15)
        v = enc[(((size_t)b * TT + t) * 64 + c) * PIX + (y - 1) * 15 + (x - 1)];
    e16[idx] = __float2half(v);
}

// ---------------------------------------------------------------------------
// Fused step: implicit-GEMM conv (9 shifted taps, 2 fp16 split passes) + gates.
// Block: 128 threads / 4 warps, tile 128M x 128N, warp tile 64x64.
// Grid (145, 4). 2 CTAs/SM.
// ---------------------------------------------------------------------------
template<int NKC, int NX, int XSTR>
__global__ __launch_bounds__(128, 2)
void step_kernel(const __half* __restrict__ xin,
                 const __half* __restrict__ hin,
                 const __half* __restrict__ Wp, const float* __restrict__ bias,
                 float* __restrict__ cst,
                 __half* __restrict__ hout)
{
    extern __shared__ __align__(16) __half smem[];
    __half* sA = smem;                          // [164][40]
    __half* sW = sA + AROWS * ALDM;             // [9][32][136]
    float* sAcc = (float*)smem;                 // reuse for epilogue

    const int m0  = blockIdx.x * 128;
    const int nt  = blockIdx.y;
    const int n0  = nt * 128;
    const int tid = threadIdx.x;
    const int wid = tid >> 5;
    const int wm  = wid >> 1;     // 0..1 : warp M offset wm*64
    const int wn  = wid & 1;      // 0..1 : warp N offset wn*64

    wmma::fragment<wmma::accumulator, 16, 16, 16, float> acc[4][4];
    #pragma unroll
    for (int f = 0; f < 4; f++)
        #pragma unroll
        for (int j = 0; j < 4; j++) wmma::fill_fragment(acc[f][j], 0.f);

    for (int kc = 0; kc < NKC; kc++) {
        // ---- stage A: rows m0-18 .. m0+145, 32 channels (fp16) ----
        const __half* src_; int coff, stride;
        if (kc < NX) { src_ = xin; coff = kc * 32; stride = XSTR; }
        else         { src_ = hin; coff = (kc - NX) * 32; stride = HID; }
        for (int u = tid; u < AROWS * 4; u += 128) {
            int r = u >> 2, q = u & 3;
            int m = m0 - 18 + r;
            uint4 v = make_uint4(0, 0, 0, 0);
            if (m >= 0 && m < MTOT)
                v = *(const uint4*)(src_ + (size_t)m * stride + coff + q * 8);
            *(uint4*)(sA + r * ALDM + q * 8) = v;
        }
        // ---- stage W hi for all 9 taps (128-col slice) ----
        for (int u = tid; u < 9 * 32 * 16; u += 128) {
            int nl  = (u & 15) * 8;
            int kr  = (u >> 4) & 31;
            int tap = u >> 9;
            const __half* s =
                Wp + ((size_t)((kc * 9 + tap) * 2 + 0)) * (32 * 512) + (size_t)kr * 512 + n0 + nl;
            *(uint4*)(sW + (tap * 32 + kr) * WLDM + nl) = *(const uint4*)s;
        }
        __syncthreads();

        // ---- pass 1: A * Wh ----
        #pragma unroll 1
        for (int tap = 0; tap < 9; tap++) {
            const int s = (tap / 3) * 17 + (tap % 3);
            #pragma unroll
            for (int ks = 0; ks < 2; ks++) {
                wmma::fragment<wmma::matrix_b, 16, 16, 16, __half, wmma::row_major> bf[4];
                #pragma unroll
                for (int j = 0; j < 4; j++)
                    wmma::load_matrix_sync(bf[j],
                        sW + (tap * 32 + ks * 16) * WLDM + wn * 64 + j * 16, WLDM);
                wmma::fragment<wmma::matrix_a, 16, 16, 16, __half, wmma::row_major> af[4];
                #pragma unroll
                for (int f = 0; f < 4; f++)
                    wmma::load_matrix_sync(af[f],
                        sA + (wm * 64 + f * 16 + s) * ALDM + ks * 16, ALDM);
                #pragma unroll
                for (int f = 0; f < 4; f++)
                    #pragma unroll
                    for (int j = 0; j < 4; j++)
                        wmma::mma_sync(acc[f][j], af[f], bf[j], acc[f][j]);
            }
        }
        __syncthreads();

        // ---- stage W lo, pass 2: A * Wl ----
        for (int u = tid; u < 9 * 32 * 16; u += 128) {
            int nl  = (u & 15) * 8;
            int kr  = (u >> 4) & 31;
            int tap = u >> 9;
            const __half* s =
                Wp + ((size_t)((kc * 9 + tap) * 2 + 1)) * (32 * 512) + (size_t)kr * 512 + n0 + nl;
            *(uint4*)(sW + (tap * 32 + kr) * WLDM + nl) = *(const uint4*)s;
        }
        __syncthreads();

        #pragma unroll 1
        for (int tap = 0; tap < 9; tap++) {
            const int s = (tap / 3) * 17 + (tap % 3);
            #pragma unroll
            for (int ks = 0; ks < 2; ks++) {
                wmma::fragment<wmma::matrix_b, 16, 16, 16, __half, wmma::row_major> bf[4];
                #pragma unroll
                for (int j = 0; j < 4; j++)
                    wmma::load_matrix_sync(bf[j],
                        sW + (tap * 32 + ks * 16) * WLDM + wn * 64 + j * 16, WLDM);
                wmma::fragment<wmma::matrix_a, 16, 16, 16, __half, wmma::row_major> af[4];
                #pragma unroll
                for (int f = 0; f < 4; f++)
                    wmma::load_matrix_sync(af[f],
                        sA + (wm * 64 + f * 16 + s) * ALDM + ks * 16, ALDM);
                #pragma unroll
                for (int f = 0; f < 4; f++)
                    #pragma unroll
                    for (int j = 0; j < 4; j++)
                        wmma::mma_sync(acc[f][j], af[f], bf[j], acc[f][j]);
            }
        }
        __syncthreads();
    }

    // ---- epilogue: acc -> smem -> unscale -> LSTM update -> fp16 state ----
    #pragma unroll
    for (int f = 0; f < 4; f++)
        #pragma unroll
        for (int j = 0; j < 4; j++)
            wmma::store_matrix_sync(sAcc + (wm * 64 + f * 16) * ACCLDM + wn * 64 + j * 16,
                                    acc[f][j], ACCLDM, wmma::mem_row_major);
    __syncthreads();

    for (int e = tid; e < 128 * 32; e += 128) {
        int mr = e >> 5, hcl = e & 31;
        int m = m0 + mr;
        if (m >= MTOT) continue;
        int pid = m % PP;
        int y = pid / 17, x = pid % 17;
        if (y < 1 || y > 15 || x < 1 || x > 15) continue;   // ring rows stay zero
        int hc = nt * 32 + hcl;
        const float* zr = &sAcc[mr * ACCLDM + hcl * 4];
        float zi = zr[0] * INVSCALE + bias[hc];
        float zf = zr[1] * INVSCALE + bias[HID + hc];
        float zo = zr[2] * INVSCALE + bias[2 * HID + hc];
        float zg = zr[3] * INVSCALE + bias[3 * HID + hc];
        float ig = __fdividef(1.f, 1.f + __expf(-zi));
        float fg = __fdividef(1.f, 1.f + __expf(-zf));
        float og = __fdividef(1.f, 1.f + __expf(-zo));
        float eg = __expf(2.f * zg);
        float gg = 1.f - __fdividef(2.f, eg + 1.f);         // tanh, inf-safe
        size_t idx = (size_t)m * HID + hc;
        float cn = fg * cst[idx] + ig * gg;
        cst[idx] = cn;
        float ec = __expf(2.f * cn);
        float hv = og * (1.f - __fdividef(2.f, ec + 1.f));
        hout[idx] = __float2half(hv);
    }
}

// ---------------------------------------------------------------------------
// Final dense (fp32): out[b,o] = feat . Wd + bd, feat = fp16 h2.
// ---------------------------------------------------------------------------
__global__ __launch_bounds__(128)
void dense_kernel(const __half* __restrict__ h2,
                  const float* __restrict__ Wd, const float* __restrict__ bd,
                  float* __restrict__ out)
{
    __shared__ float sf[1024];
    const int b = blockIdx.x;
    const int o = threadIdx.x;
    float s0 = 0.f, s1 = 0.f, s2 = 0.f, s3 = 0.f;
    const int KTOT = HID * PIX;                // 28800
    for (int k0 = 0; k0 < KTOT; k0 += 1024) {
        __syncthreads();
        for (int i = o; i < 1024; i += 128) {
            int k = k0 + i;
            float v = 0.f;
            if (k < KTOT) {
                int hc = k / PIX, p = k % PIX;
                size_t m = (size_t)b * PP + (p / 15 + 1) * 17 + (p % 15 + 1);
                v = __half2float(h2[m * HID + hc]);
            }
            sf[i] = v;
        }
        __syncthreads();
        int kmax = min(1024, KTOT - k0);
        for (int kk = 0; kk < kmax; kk += 4) {
            s0 += sf[kk + 0] * Wd[(long)(k0 + kk + 0) * 128 + o];
            s1 += sf[kk + 1] * Wd[(long)(k0 + kk + 1) * 128 + o];
            s2 += sf[kk + 2] * Wd[(long)(k0 + kk + 2) * 128 + o];
            s3 += sf[kk + 3] * Wd[(long)(k0 + kk + 3) * 128 + o];
        }
    }
    out[b * 128 + o] = (s0 + s1) + (s2 + s3) + bd[o];
}

// ---------------------------------------------------------------------------
extern "C" void kernel_launch(void* const* d_in, const int* in_sizes, int n_in,
                              void* d_out, int out_size)
{
    const float* enc = (const float*)d_in[0];
    const float* W0  = (const float*)d_in[1];
    const float* b0  = (const float*)d_in[2];
    const float* W1  = (const float*)d_in[3];
    const float* b1  = (const float*)d_in[4];
    const float* Wd  = (const float*)d_in[5];
    const float* bd  = (const float*)d_in[6];
    float* out = (float*)d_out;

    __half *e16, *h1, *h2, *Wp0, *Wp1;
    float *c1, *c2;
    cudaGetSymbolAddress((void**)&e16, g_enc);
    cudaGetSymbolAddress((void**)&h1, g_h1);
    cudaGetSymbolAddress((void**)&h2, g_h2);
    cudaGetSymbolAddress((void**)&c1, g_c1);
    cudaGetSymbolAddress((void**)&c2, g_c2);
    cudaGetSymbolAddress((void**)&Wp0, g_Wp0);
    cudaGetSymbolAddress((void**)&Wp1, g_Wp1);

    const size_t HS = (size_t)MTOT * HID;

    cudaMemsetAsync(h1, 0, 2 * HS * sizeof(__half), 0);
    cudaMemsetAsync(h2, 0, 2 * HS * sizeof(__half), 0);
    cudaMemsetAsync(c1, 0, HS * sizeof(float), 0);
    cudaMemsetAsync(c2, 0, HS * sizeof(float), 0);

    prep_w<<<(6 * 9 * 32 * 512 + 255) / 256, 256>>>(W0, Wp0, 6);
    prep_w<<<(8 * 9 * 32 * 512 + 255) / 256, 256>>>(W1, Wp1, 8);
    {
        size_t tot = (size_t)TT * MTOT * 64;
        prep_enc<<<(unsigned)((tot + 255) / 256), 256>>>(enc, e16);
    }

    cudaFuncSetAttribute(step_kernel<6, 2, 64>,
                         cudaFuncAttributeMaxDynamicSharedMemorySize, SMEM_BYTES);
    cudaFuncSetAttribute(step_kernel<8, 4, 128>,
                         cudaFuncAttributeMaxDynamicSharedMemorySize, SMEM_BYTES);

    dim3 grid(MT, 4);
    for (int t = 0; t < TT; t++) {
        const int rd = t & 1, wr = rd ^ 1;
        step_kernel<6, 2, 64><<<grid, 128, SMEM_BYTES>>>(
            e16 + (size_t)t * MTOT * 64,
            h1 + (size_t)rd * HS,
            Wp0, b0, c1,
            h1 + (size_t)wr * HS);
        step_kernel<8, 4, 128><<<grid, 128, SMEM_BYTES>>>(
            h1 + (size_t)wr * HS,
            h2 + (size_t)rd * HS,
            Wp1, b1, c2,
            h2 + (size_t)wr * HS);
    }
    // final h2 in ping 0 (wr of t=47)
    dense_kernel<<<BATCH, 128>>>(h2, Wd, bd, out);
}